// round 7
// baseline (speedup 1.0000x reference)
#include <cuda_runtime.h>
#include <cstddef>

#define FFT_N 8192
#define NT    1024
#define CH    64

// XOR swizzle on float2 index: conflict-free (<=2-way worst case) for all
// access patterns used here.
#define SWZ(a) ((a) ^ (((a) >> 4) & 15))

__device__ __forceinline__ float2 cmul(float2 a, float2 b) {
    return make_float2(fmaf(a.x, b.x, -a.y * b.y), fmaf(a.x, b.y, a.y * b.x));
}
__device__ __forceinline__ float2 cadd(float2 a, float2 b) { return make_float2(a.x + b.x, a.y + b.y); }
__device__ __forceinline__ float2 csub(float2 a, float2 b) { return make_float2(a.x - b.x, a.y - b.y); }

template<int DIR>
__device__ __forceinline__ void dft4(float2& a, float2& b, float2& c, float2& d) {
    float2 t0 = cadd(a, c), t1 = csub(a, c);
    float2 t2 = cadd(b, d), t3 = csub(b, d);
    a = cadd(t0, t2);
    c = csub(t0, t2);
    if (DIR > 0) {
        b = make_float2(t1.x + t3.y, t1.y - t3.x);
        d = make_float2(t1.x - t3.y, t1.y + t3.x);
    } else {
        b = make_float2(t1.x - t3.y, t1.y + t3.x);
        d = make_float2(t1.x + t3.y, t1.y - t3.x);
    }
}

// In-place DFT8, natural-order outputs.
template<int DIR>
__device__ __forceinline__ void dft8(float2 v[8]) {
    dft4<DIR>(v[0], v[2], v[4], v[6]);
    dft4<DIR>(v[1], v[3], v[5], v[7]);
    const float C2 = 0.70710678118654752f;
    const float s  = (DIR > 0) ? 1.0f : -1.0f;
    v[3] = cmul(v[3], make_float2( C2, -s * C2));
    v[5] = cmul(v[5], make_float2(0.f, -s      ));
    v[7] = cmul(v[7], make_float2(-C2, -s * C2));
    float2 y[8];
    #pragma unroll
    for (int k2 = 0; k2 < 4; k2++) {
        y[k2]     = cadd(v[2 * k2], v[2 * k2 + 1]);
        y[k2 + 4] = csub(v[2 * k2], v[2 * k2 + 1]);
    }
    #pragma unroll
    for (int o = 0; o < 8; o++) v[o] = y[o];
}

template<int S, int DIR>
__device__ __forceinline__ void stage_read(const float2* __restrict__ buf, int j,
                                           float2 w1, float2 v[8]) {
    #pragma unroll
    for (int r = 0; r < 8; r++)
        v[r] = buf[SWZ(j + r * (FFT_N / 8))];
    if (S > 1) {
        float2 w = w1;
        #pragma unroll
        for (int r = 1; r < 8; r++) {
            v[r] = cmul(v[r], w);
            if (r < 7) w = cmul(w, w1);
        }
    }
    dft8<DIR>(v);
}

template<int S>
__device__ __forceinline__ void stage_write(float2* __restrict__ buf, int j,
                                            const float2 v[8]) {
    const int jq   = j & (S - 1);
    const int base = jq + (j / S) * (S * 8);
    #pragma unroll
    for (int o = 0; o < 8; o++)
        buf[SWZ(base + S * o)] = v[o];
}

// One in-place radix-8 stage applied to both buffers (guarded per pair).
template<int S, int DIR>
__device__ __forceinline__ void stage_pair(float2* b0, float2* b1, int j,
                                           bool p0, bool p1) {
    float2 w1 = make_float2(1.f, 0.f);
    if (S > 1) {
        float ss, cc;
        sincospif((DIR > 0 ? -2.0f : 2.0f) * (float)(j & (S - 1)) / (8.0f * (float)S), &ss, &cc);
        w1 = make_float2(cc, ss);
    }
    float2 v[8];
    if (p0) stage_read<S, DIR>(b0, j, w1, v);
    __syncthreads();
    if (p0) stage_write<S>(b0, j, v);
    if (p1) stage_read<S, DIR>(b1, j, w1, v);
    __syncthreads();
    if (p1) stage_write<S>(b1, j, v);
    __syncthreads();
}

// Hermitian rebuild for one (ka, kb=(N-ka)%N) pair of one buffer:
// unpack the packed FFT Z into per-channel amplitudes, apply random phases,
// re-symmetrize into W = H_A + i*H_B. Writes W in place.
__device__ __forceinline__ void rebuild(float2* __restrict__ buf, int ka, int kb,
                                        float2 Za, float2 Zb,
                                        float2 phA, float2 phB) {
    const float TWO_PI = 6.283185307179586476925f;
    const float scale  = 0.25f / (float)FFT_N;
    float ax = Za.x + Zb.x, ay = Za.y - Zb.y;
    float bx = Za.y + Zb.y, by = Zb.x - Za.x;
    float ampA = sqrtf(fmaf(ax, ax, ay * ay)) * scale;
    float ampB = sqrtf(fmaf(bx, bx, by * by)) * scale;
    float sA1, cA1, sA2, cA2, sB1, cB1, sB2, cB2;
    __sincosf(TWO_PI * phA.x, &sA1, &cA1);
    __sincosf(TWO_PI * phA.y, &sA2, &cA2);
    __sincosf(TWO_PI * phB.x, &sB1, &cB1);
    __sincosf(TWO_PI * phB.y, &sB2, &cB2);
    float h1x = ampA * (cA1 + cA2), h1y = ampA * (sA1 - sA2);
    float h2x = ampB * (cB1 + cB2), h2y = ampB * (sB1 - sB2);
    buf[SWZ(ka)] = make_float2(h1x - h2y, h1y + h2x);
    buf[SWZ(kb)] = make_float2(h1x + h2y, h2x - h1y);
}

__global__ __launch_bounds__(NT, 1)
void surrogate_kernel(const float* __restrict__ wave,
                      const float* __restrict__ phases,
                      const float* __restrict__ mask,
                      float* __restrict__ out) {
    const int blk = blockIdx.x;
    const int b   = blk >> 4;
    const int c0  = (blk & 15) * 4;
    const int tid = threadIdx.x;

    const bool s0 = mask[b * CH + c0]     < 0.5f;
    const bool s1 = mask[b * CH + c0 + 1] < 0.5f;
    const bool s2 = mask[b * CH + c0 + 2] < 0.5f;
    const bool s3 = mask[b * CH + c0 + 3] < 0.5f;
    const bool p0 = s0 | s1;
    const bool p1 = s2 | s3;
    const bool m0 = p0 && !(s0 && s1);   // pair0 mixed: one kept lane -> stash
    const bool m1 = p1 && !(s2 && s3);

    const float4* w4 = (const float4*)(wave   + (size_t)b * FFT_N * CH + c0);
    const float4* p4 = (const float4*)(phases + (size_t)b * FFT_N * CH + c0);
    float4*       o4 = (float4*)      (out    + (size_t)b * FFT_N * CH + c0);

    if (!p0 && !p1) {
        #pragma unroll 4
        for (int t = tid; t < FFT_N; t += NT)
            o4[(size_t)t * 16] = w4[(size_t)t * 16];
        return;
    }

    extern __shared__ float2 sm[];
    float2* b0    = sm;                        // pair 0: ch c0 + i*ch(c0+1)
    float2* b1    = sm + FFT_N;                // pair 1: ch c0+2 + i*ch(c0+3)
    float*  stash = (float*)(sm + 2 * FFT_N);  // kept-lane originals, 2 x 8192 floats

    // ---- Load: one float4 per sample -> both buffers (+stash kept lanes) --
    #pragma unroll
    for (int i = 0; i < FFT_N / NT; i++) {
        int t = tid + i * NT;
        float4 g = w4[(size_t)t * 16];
        b0[SWZ(t)] = make_float2(g.x, g.y);
        b1[SWZ(t)] = make_float2(g.z, g.w);
        if (m0) stash[t]         = s0 ? g.y : g.x;
        if (m1) stash[FFT_N + t] = s2 ? g.w : g.z;
    }
    __syncthreads();

    // ---- Forward FFT: radix-8 x4 in place + radix-2 -------------------------
    stage_pair<1,   1>(b0, b1, tid, p0, p1);
    stage_pair<8,   1>(b0, b1, tid, p0, p1);
    stage_pair<64,  1>(b0, b1, tid, p0, p1);
    stage_pair<512, 1>(b0, b1, tid, p0, p1);
    #pragma unroll
    for (int i = 0; i < FFT_N / 2 / NT; i++) {
        int j = tid + i * NT;
        float ss, cc;
        sincospif(-(float)j / 4096.0f, &ss, &cc);
        float2 w = make_float2(cc, ss);
        if (p0) {
            float2 u0 = b0[SWZ(j)], u1 = cmul(b0[SWZ(j + 4096)], w);
            b0[SWZ(j)] = cadd(u0, u1);  b0[SWZ(j + 4096)] = csub(u0, u1);
        }
        if (p1) {
            float2 u0 = b1[SWZ(j)], u1 = cmul(b1[SWZ(j + 4096)], w);
            b1[SWZ(j)] = cadd(u0, u1);  b1[SWZ(j + 4096)] = csub(u0, u1);
        }
    }
    __syncthreads();

    // ---- Spectrum rebuild (in place; thread owns pair (k, nk)) -------------
    for (int k = tid; k <= FFT_N / 2; k += NT) {
        const int nk = (FFT_N - k) & (FFT_N - 1);
        float4 pk  = p4[(size_t)k  * 16];
        float4 pnk = p4[(size_t)nk * 16];
        if (p0) {
            float2 Za = b0[SWZ(k)], Zb = b0[SWZ(nk)];
            rebuild(b0, k, nk, Za, Zb, make_float2(pk.x, pnk.x), make_float2(pk.y, pnk.y));
        }
        if (p1) {
            float2 Za = b1[SWZ(k)], Zb = b1[SWZ(nk)];
            rebuild(b1, k, nk, Za, Zb, make_float2(pk.z, pnk.z), make_float2(pk.w, pnk.w));
        }
    }
    __syncthreads();

    // ---- Inverse FFT --------------------------------------------------------
    stage_pair<1,   -1>(b0, b1, tid, p0, p1);
    stage_pair<8,   -1>(b0, b1, tid, p0, p1);
    stage_pair<64,  -1>(b0, b1, tid, p0, p1);
    stage_pair<512, -1>(b0, b1, tid, p0, p1);

    // ---- Final inverse radix-2 + select + float4 store (no gmem reload) ----
    #pragma unroll
    for (int i = 0; i < FFT_N / 2 / NT; i++) {
        int j = tid + i * NT;
        float ss, cc;
        sincospif((float)j / 4096.0f, &ss, &cc);
        float2 w = make_float2(cc, ss);
        float2 y0, y1, z0, z1;
        if (p0) {
            float2 u0 = b0[SWZ(j)], u1 = cmul(b0[SWZ(j + 4096)], w);
            y0 = cadd(u0, u1);  y1 = csub(u0, u1);
            if (m0) {
                float oa = stash[j], ob = stash[j + 4096];
                if (s0) { y0.y = oa; y1.y = ob; }   // ch1 kept
                else    { y0.x = oa; y1.x = ob; }   // ch0 kept
            }
        } else {   // pair fully kept: buffer still holds the originals
            y0 = b0[SWZ(j)];  y1 = b0[SWZ(j + 4096)];
        }
        if (p1) {
            float2 u0 = b1[SWZ(j)], u1 = cmul(b1[SWZ(j + 4096)], w);
            z0 = cadd(u0, u1);  z1 = csub(u0, u1);
            if (m1) {
                float oa = stash[FFT_N + j], ob = stash[FFT_N + j + 4096];
                if (s2) { z0.y = oa; z1.y = ob; }
                else    { z0.x = oa; z1.x = ob; }
            }
        } else {
            z0 = b1[SWZ(j)];  z1 = b1[SWZ(j + 4096)];
        }
        o4[(size_t)j * 16]          = make_float4(y0.x, y0.y, z0.x, z0.y);
        o4[(size_t)(j + 4096) * 16] = make_float4(y1.x, y1.y, z1.x, z1.y);
    }
}

extern "C" void kernel_launch(void* const* d_in, const int* in_sizes, int n_in,
                              void* d_out, int out_size) {
    const float* wave   = (const float*)d_in[0];
    const float* phases = (const float*)d_in[1];
    const float* maskp  = (const float*)d_in[2];
    float* out = (float*)d_out;

    const int B = in_sizes[0] / (FFT_N * CH);
    const int smem = 2 * FFT_N * (int)sizeof(float2) + 2 * FFT_N * (int)sizeof(float); // 196,608 B

    cudaFuncSetAttribute(surrogate_kernel,
                         cudaFuncAttributeMaxDynamicSharedMemorySize, smem);
    surrogate_kernel<<<B * (CH / 4), NT, smem>>>(wave, phases, maskp, out);
}

// round 8
// speedup vs baseline: 1.0380x; 1.0380x over previous
#include <cuda_runtime.h>
#include <cstddef>

#define FFT_N 8192
#define NT    1024
#define CH    64

// XOR swizzle on float2 index: conflict-free (<=2-way worst case) for all
// access patterns used here.
#define SWZ(a) ((a) ^ (((a) >> 4) & 15))

__device__ __forceinline__ float2 cmul(float2 a, float2 b) {
    return make_float2(fmaf(a.x, b.x, -a.y * b.y), fmaf(a.x, b.y, a.y * b.x));
}
__device__ __forceinline__ float2 cadd(float2 a, float2 b) { return make_float2(a.x + b.x, a.y + b.y); }
__device__ __forceinline__ float2 csub(float2 a, float2 b) { return make_float2(a.x - b.x, a.y - b.y); }

template<int DIR>
__device__ __forceinline__ void dft4(float2& a, float2& b, float2& c, float2& d) {
    float2 t0 = cadd(a, c), t1 = csub(a, c);
    float2 t2 = cadd(b, d), t3 = csub(b, d);
    a = cadd(t0, t2);
    c = csub(t0, t2);
    if (DIR > 0) {
        b = make_float2(t1.x + t3.y, t1.y - t3.x);
        d = make_float2(t1.x - t3.y, t1.y + t3.x);
    } else {
        b = make_float2(t1.x - t3.y, t1.y + t3.x);
        d = make_float2(t1.x + t3.y, t1.y - t3.x);
    }
}

// In-place DFT8, natural-order outputs.
template<int DIR>
__device__ __forceinline__ void dft8(float2 v[8]) {
    dft4<DIR>(v[0], v[2], v[4], v[6]);
    dft4<DIR>(v[1], v[3], v[5], v[7]);
    const float C2 = 0.70710678118654752f;
    const float s  = (DIR > 0) ? 1.0f : -1.0f;
    v[3] = cmul(v[3], make_float2( C2, -s * C2));
    v[5] = cmul(v[5], make_float2(0.f, -s      ));
    v[7] = cmul(v[7], make_float2(-C2, -s * C2));
    float2 y[8];
    #pragma unroll
    for (int k2 = 0; k2 < 4; k2++) {
        y[k2]     = cadd(v[2 * k2], v[2 * k2 + 1]);
        y[k2 + 4] = csub(v[2 * k2], v[2 * k2 + 1]);
    }
    #pragma unroll
    for (int o = 0; o < 8; o++) v[o] = y[o];
}

// Out-of-place radix-8 Stockham DIT stage: src -> dst, one butterfly/thread.
// No intra-stage hazards: 8 clean LDS, compute, 8 STS. Caller places the bar.
template<int S, int DIR>
__device__ __forceinline__ void stage_oop(const float2* __restrict__ src,
                                          float2* __restrict__ dst, int j) {
    float2 v[8];
    #pragma unroll
    for (int r = 0; r < 8; r++)
        v[r] = src[SWZ(j + r * (FFT_N / 8))];
    const int jq = j & (S - 1);
    if (S > 1) {
        float ss, cc;
        sincospif((DIR > 0 ? -2.0f : 2.0f) * (float)jq / (8.0f * (float)S), &ss, &cc);
        float2 w1 = make_float2(cc, ss);
        float2 w  = w1;
        #pragma unroll
        for (int r = 1; r < 8; r++) {
            v[r] = cmul(v[r], w);
            if (r < 7) w = cmul(w, w1);
        }
    }
    dft8<DIR>(v);
    const int base = jq + (j / S) * (S * 8);
    #pragma unroll
    for (int o = 0; o < 8; o++)
        dst[SWZ(base + S * o)] = v[o];
}

// Four radix-8 stages ping-ponging buf <-> scr; result lands back in buf.
template<int DIR>
__device__ __forceinline__ void fft_r8x4(float2* buf, float2* scr, int j) {
    stage_oop<1,   DIR>(buf, scr, j); __syncthreads();
    stage_oop<8,   DIR>(scr, buf, j); __syncthreads();
    stage_oop<64,  DIR>(buf, scr, j); __syncthreads();
    stage_oop<512, DIR>(scr, buf, j); __syncthreads();
}

// Hermitian rebuild for one (ka, kb=(N-ka)%N) pair of one buffer:
// unpack packed FFT Z into per-channel amplitudes, apply random phases,
// re-symmetrize into W = H_A + i*H_B. Writes W in place.
__device__ __forceinline__ void rebuild(float2* __restrict__ buf, int ka, int kb,
                                        float2 Za, float2 Zb,
                                        float2 phA, float2 phB) {
    const float TWO_PI = 6.283185307179586476925f;
    const float scale  = 0.25f / (float)FFT_N;
    float ax = Za.x + Zb.x, ay = Za.y - Zb.y;
    float bx = Za.y + Zb.y, by = Zb.x - Za.x;
    float ampA = sqrtf(fmaf(ax, ax, ay * ay)) * scale;
    float ampB = sqrtf(fmaf(bx, bx, by * by)) * scale;
    float sA1, cA1, sA2, cA2, sB1, cB1, sB2, cB2;
    __sincosf(TWO_PI * phA.x, &sA1, &cA1);
    __sincosf(TWO_PI * phA.y, &sA2, &cA2);
    __sincosf(TWO_PI * phB.x, &sB1, &cB1);
    __sincosf(TWO_PI * phB.y, &sB2, &cB2);
    float h1x = ampA * (cA1 + cA2), h1y = ampA * (sA1 - sA2);
    float h2x = ampB * (cB1 + cB2), h2y = ampB * (sB1 - sB2);
    buf[SWZ(ka)] = make_float2(h1x - h2y, h1y + h2x);
    buf[SWZ(kb)] = make_float2(h1x + h2y, h2x - h1y);
}

__global__ __launch_bounds__(NT, 1)
void surrogate_kernel(const float* __restrict__ wave,
                      const float* __restrict__ phases,
                      const float* __restrict__ mask,
                      float* __restrict__ out) {
    const int blk = blockIdx.x;
    const int b   = blk >> 4;
    const int c0  = (blk & 15) * 4;
    const int tid = threadIdx.x;

    const bool s0 = mask[b * CH + c0]     < 0.5f;
    const bool s1 = mask[b * CH + c0 + 1] < 0.5f;
    const bool s2 = mask[b * CH + c0 + 2] < 0.5f;
    const bool s3 = mask[b * CH + c0 + 3] < 0.5f;
    const bool p0 = s0 | s1;
    const bool p1 = s2 | s3;

    const float4* w4 = (const float4*)(wave   + (size_t)b * FFT_N * CH + c0);
    const float4* p4 = (const float4*)(phases + (size_t)b * FFT_N * CH + c0);
    float4*       o4 = (float4*)      (out    + (size_t)b * FFT_N * CH + c0);

    if (!p0 && !p1) {
        #pragma unroll 4
        for (int t = tid; t < FFT_N; t += NT)
            o4[(size_t)t * 16] = w4[(size_t)t * 16];
        return;
    }

    extern __shared__ float2 sm[];
    float2* A = sm;                // pair 0: ch c0 + i*ch(c0+1)
    float2* B = sm + FFT_N;        // pair 1: ch c0+2 + i*ch(c0+3)
    float2* C = sm + 2 * FFT_N;    // shared scratch

    // ---- Load: one float4 per time sample -> both buffers -----------------
    #pragma unroll
    for (int i = 0; i < FFT_N / NT; i++) {
        int t = tid + i * NT;
        float4 g = w4[(size_t)t * 16];
        A[SWZ(t)] = make_float2(g.x, g.y);
        B[SWZ(t)] = make_float2(g.z, g.w);
    }
    __syncthreads();

    // ---- Forward FFT: sequential per-pair, out-of-place ping-pong ---------
    if (p0) fft_r8x4<1>(A, C, tid);   // p0 is CTA-uniform: bars are safe
    if (p1) fft_r8x4<1>(B, C, tid);

    // ---- Forward radix-2 (in place, thread-local slots) --------------------
    #pragma unroll
    for (int i = 0; i < FFT_N / 2 / NT; i++) {
        int j = tid + i * NT;
        float ss, cc;
        sincospif(-(float)j / 4096.0f, &ss, &cc);
        float2 w = make_float2(cc, ss);
        if (p0) {
            float2 u0 = A[SWZ(j)], u1 = cmul(A[SWZ(j + 4096)], w);
            A[SWZ(j)] = cadd(u0, u1);  A[SWZ(j + 4096)] = csub(u0, u1);
        }
        if (p1) {
            float2 u0 = B[SWZ(j)], u1 = cmul(B[SWZ(j + 4096)], w);
            B[SWZ(j)] = cadd(u0, u1);  B[SWZ(j + 4096)] = csub(u0, u1);
        }
    }
    __syncthreads();

    // ---- Spectrum rebuild (shared pass: phases loaded once) ---------------
    for (int k = tid; k <= FFT_N / 2; k += NT) {
        const int nk = (FFT_N - k) & (FFT_N - 1);
        float4 pk  = p4[(size_t)k  * 16];
        float4 pnk = p4[(size_t)nk * 16];
        if (p0) {
            float2 Za = A[SWZ(k)], Zb = A[SWZ(nk)];
            rebuild(A, k, nk, Za, Zb, make_float2(pk.x, pnk.x), make_float2(pk.y, pnk.y));
        }
        if (p1) {
            float2 Za = B[SWZ(k)], Zb = B[SWZ(nk)];
            rebuild(B, k, nk, Za, Zb, make_float2(pk.z, pnk.z), make_float2(pk.w, pnk.w));
        }
    }
    __syncthreads();

    // ---- Inverse FFT: sequential per-pair ----------------------------------
    if (p0) fft_r8x4<-1>(A, C, tid);
    if (p1) fft_r8x4<-1>(B, C, tid);

    // ---- Final inverse radix-2 fused with select + float4 store ------------
    const bool all4 = s0 & s1 & s2 & s3;
    #pragma unroll
    for (int i = 0; i < FFT_N / 2 / NT; i++) {
        int j = tid + i * NT;
        float ss, cc;
        sincospif((float)j / 4096.0f, &ss, &cc);
        float2 w = make_float2(cc, ss);
        float2 y0, y1, z0, z1;
        if (p0) {
            float2 u0 = A[SWZ(j)], u1 = cmul(A[SWZ(j + 4096)], w);
            y0 = cadd(u0, u1);  y1 = csub(u0, u1);
        } else {   // pair fully kept: A still holds the originals
            y0 = A[SWZ(j)];  y1 = A[SWZ(j + 4096)];
        }
        if (p1) {
            float2 u0 = B[SWZ(j)], u1 = cmul(B[SWZ(j + 4096)], w);
            z0 = cadd(u0, u1);  z1 = csub(u0, u1);
        } else {
            z0 = B[SWZ(j)];  z1 = B[SWZ(j + 4096)];
        }
        if (all4) {
            o4[(size_t)j * 16]          = make_float4(y0.x, y0.y, z0.x, z0.y);
            o4[(size_t)(j + 4096) * 16] = make_float4(y1.x, y1.y, z1.x, z1.y);
        } else {
            float4 ga = w4[(size_t)j * 16];
            float4 gb = w4[(size_t)(j + 4096) * 16];
            o4[(size_t)j * 16] = make_float4(s0 ? y0.x : ga.x, s1 ? y0.y : ga.y,
                                             s2 ? z0.x : ga.z, s3 ? z0.y : ga.w);
            o4[(size_t)(j + 4096) * 16] = make_float4(s0 ? y1.x : gb.x, s1 ? y1.y : gb.y,
                                                      s2 ? z1.x : gb.z, s3 ? z1.y : gb.w);
        }
    }
}

extern "C" void kernel_launch(void* const* d_in, const int* in_sizes, int n_in,
                              void* d_out, int out_size) {
    const float* wave   = (const float*)d_in[0];
    const float* phases = (const float*)d_in[1];
    const float* maskp  = (const float*)d_in[2];
    float* out = (float*)d_out;

    const int B = in_sizes[0] / (FFT_N * CH);
    const int smem = 3 * FFT_N * (int)sizeof(float2);   // 196,608 B

    cudaFuncSetAttribute(surrogate_kernel,
                         cudaFuncAttributeMaxDynamicSharedMemorySize, smem);
    surrogate_kernel<<<B * (CH / 4), NT, smem>>>(wave, phases, maskp, out);
}